// round 16
// baseline (speedup 1.0000x reference)
#include <cuda_runtime.h>
#include <cuda_fp16.h>
#include <math.h>
#include <stdint.h>

// ---------------------------------------------------------------------------
// Problem constants
// ---------------------------------------------------------------------------
#define MAX_NODES 50000
#define MAX_EDGES 800000
#define DHID      256
#define DH8       32          // DHID / 8 (uint4 chunks of half)
#define NGRAPHS   64
#define DIN       768
#define MAXB      64

// ---------------------------------------------------------------------------
// Scratch (static device globals)
// ---------------------------------------------------------------------------
__device__ __align__(16) __half g_hh  [MAX_NODES * DHID];  // GEMM output (fp16)
__device__ __align__(16) __half g_aggh[MAX_NODES * DHID];  // aggregated (fp16)
__device__ __align__(16) __half g_w1h [DIN * DHID];        // fp16 weights [K,N]
__device__ __align__(16) __half g_w2h [DHID * DHID];
__device__ __align__(16) __half g_w3h [DHID * DHID];
__device__ float g_dinv[MAX_NODES];
__device__ int   g_edeg[MAX_NODES];
__device__ int   g_off [MAX_NODES + 1];
__device__ int   g_cur [MAX_NODES];
__device__ int   g_csr [MAX_EDGES];
__device__ float g_pool[NGRAPHS * DHID];
__device__ int   g_gstart[NGRAPHS + 1];
__device__ int   g_bsum[MAXB];
__device__ int   g_bofs[MAXB];

// ---------------------------------------------------------------------------
// init: zero histogram/cursors/pool, init gstart, convert weights to fp16.
// ---------------------------------------------------------------------------
__global__ void init_kernel(const float* __restrict__ W1,
                            const float* __restrict__ W2,
                            const float* __restrict__ W3, int n) {
    int i = blockIdx.x * blockDim.x + threadIdx.x;
    if (i < n) { g_edeg[i] = 0; g_cur[i] = 0; }
    if (i <= NGRAPHS) g_gstart[i] = n;
    if (i < NGRAPHS * DHID) g_pool[i] = 0.f;
    if (i < DIN * DHID) g_w1h[i] = __float2half(W1[i]);
    if (i < DHID * DHID) {
        g_w2h[i] = __float2half(W2[i]);
        g_w3h[i] = __float2half(W3[i]);
    }
}

// hist + graph-start min, fused (grid covers max(E, n))
__global__ void histgmin_kernel(const int* __restrict__ dst,
                                const int* __restrict__ batch, int E, int n) {
    int i = blockIdx.x * blockDim.x + threadIdx.x;
    if (i < E) atomicAdd(&g_edeg[dst[i]], 1);
    if (i < n) atomicMin(&g_gstart[batch[i]], i);
}

__global__ void dinv_kernel(int n) {
    int i = blockIdx.x * blockDim.x + threadIdx.x;
    if (i < n) g_dinv[i] = rsqrtf((float)(g_edeg[i] + 1));
}

__global__ __launch_bounds__(1024)
void scan1_kernel(int n) {
    __shared__ int ws[32];
    const int tid = threadIdx.x;
    const int b = blockIdx.x;
    const int i = b * 1024 + tid;
    int v = (i < n) ? g_edeg[i] : 0;
    int x = v;
    #pragma unroll
    for (int ofs = 1; ofs < 32; ofs <<= 1) {
        int y = __shfl_up_sync(0xFFFFFFFFu, x, ofs);
        if ((tid & 31) >= ofs) x += y;
    }
    if ((tid & 31) == 31) ws[tid >> 5] = x;
    __syncthreads();
    if (tid < 32) {
        int w = ws[tid];
        #pragma unroll
        for (int ofs = 1; ofs < 32; ofs <<= 1) {
            int y = __shfl_up_sync(0xFFFFFFFFu, w, ofs);
            if (tid >= ofs) w += y;
        }
        ws[tid] = w;
    }
    __syncthreads();
    int incl = x + ((tid >= 32) ? ws[(tid >> 5) - 1] : 0);
    if (i < n) g_off[i] = incl - v;
    if (tid == 1023) g_bsum[b] = incl;
}

__global__ void scan2_kernel(int nb, int n) {
    if (threadIdx.x == 0) {
        int run = 0;
        for (int b = 0; b < nb; b++) { g_bofs[b] = run; run += g_bsum[b]; }
        g_off[n] = run;
    }
}

__global__ __launch_bounds__(1024)
void scan3_kernel(int n) {
    int i = blockIdx.x * blockDim.x + threadIdx.x;
    if (i < n) g_off[i] += g_bofs[i >> 10];
}

__global__ void scatter_kernel(const int* __restrict__ src,
                               const int* __restrict__ dst, int E) {
    int i = blockIdx.x * blockDim.x + threadIdx.x;
    if (i < E) {
        int d = dst[i];
        int pos = g_off[d] + atomicAdd(&g_cur[d], 1);
        g_csr[pos] = src[i];
    }
}

__global__ void gfix_kernel(int n) {
    if (threadIdx.x == 0 && blockIdx.x == 0) {
        g_gstart[NGRAPHS] = n;
        for (int g = NGRAPHS - 1; g >= 0; g--)
            if (g_gstart[g] > g_gstart[g + 1]) g_gstart[g] = g_gstart[g + 1];
    }
}

// ---------------------------------------------------------------------------
// fp16 tensor-core GEMM (fp32 accumulate): g_hh = A @ B, C stored fp16.
// CTA tile 128x64x32, 8 warps (4 M x 2 N), warp tile 32x32 via m16n8k16.
// __launch_bounds__(256,3): cap regs ~85 for 3 CTAs/SM (24 warps, latency fix).
// HA=true : A fp16 (g_aggh); HA=false: A fp32 (x), cvt on the fly.
// ---------------------------------------------------------------------------
#define TBM 128
#define TBN 64
#define TBK 32
#define APADH 8
#define BPADH 8
#define AROW (TBK + APADH)    // 40 half = 80 B
#define BROW (TBN + BPADH)    // 72 half = 144 B

__device__ __forceinline__ void ldsm_x4(uint32_t& r0, uint32_t& r1,
                                        uint32_t& r2, uint32_t& r3, uint32_t addr) {
    asm volatile("ldmatrix.sync.aligned.m8n8.x4.shared.b16 {%0,%1,%2,%3}, [%4];"
                 : "=r"(r0), "=r"(r1), "=r"(r2), "=r"(r3) : "r"(addr));
}

__device__ __forceinline__ void ldsm_x4_t(uint32_t& r0, uint32_t& r1,
                                          uint32_t& r2, uint32_t& r3, uint32_t addr) {
    asm volatile("ldmatrix.sync.aligned.m8n8.x4.trans.shared.b16 {%0,%1,%2,%3}, [%4];"
                 : "=r"(r0), "=r"(r1), "=r"(r2), "=r"(r3) : "r"(addr));
}

__device__ __forceinline__ void mma_f16(float* c, const uint32_t* a, const uint32_t* b) {
    asm volatile(
        "mma.sync.aligned.m16n8k16.row.col.f32.f16.f16.f32 "
        "{%0,%1,%2,%3}, {%4,%5,%6,%7}, {%8,%9}, {%0,%1,%2,%3};"
        : "+f"(c[0]), "+f"(c[1]), "+f"(c[2]), "+f"(c[3])
        : "r"(a[0]), "r"(a[1]), "r"(a[2]), "r"(a[3]), "r"(b[0]), "r"(b[1]));
}

__device__ __forceinline__ uint2 pack4h(float4 v) {
    __half2 h0 = __floats2half2_rn(v.x, v.y);
    __half2 h1 = __floats2half2_rn(v.z, v.w);
    uint2 u;
    u.x = *(uint32_t*)&h0;
    u.y = *(uint32_t*)&h1;
    return u;
}

template <bool HA>
__global__ __launch_bounds__(256, 3)
void gemm_tc_kernel(const float* __restrict__ Af, const __half* __restrict__ Ahg,
                    const __half* __restrict__ Bg, int M, int K, int N) {
    __half* __restrict__ C = g_hh;

    __shared__ __align__(16) __half Ah[2][TBM][AROW];
    __shared__ __align__(16) __half Bh[2][TBK][BROW];

    const int tid  = threadIdx.x;
    const int warp = tid >> 5;
    const int lane = tid & 31;
    const int g    = lane >> 2;
    const int t    = lane & 3;
    const int wm   = warp >> 1;             // 0..3 (M)
    const int wn   = warp & 1;              // 0..1 (N)
    const int row0 = blockIdx.y * TBM;
    const int col0 = blockIdx.x * TBN;
    const int mbase = wm * 32;
    const int nbase = wn * 32;

    const int lquad = lane & 15;
    const int lhalf = (lane >> 4) << 3;

    const uint32_t a_smem0 = (uint32_t)__cvta_generic_to_shared(&Ah[0][0][0]);
    const uint32_t b_smem0 = (uint32_t)__cvta_generic_to_shared(&Bh[0][0][0]);
    const uint32_t a_buf_sz = TBM * AROW * 2;
    const uint32_t b_buf_sz = TBK * BROW * 2;

    float acc[2][4][4];
    #pragma unroll
    for (int mi = 0; mi < 2; mi++)
        #pragma unroll
        for (int ni = 0; ni < 4; ni++)
            #pragma unroll
            for (int r = 0; r < 4; r++) acc[mi][ni][r] = 0.f;

    // ---- prologue: tile 0 -> buf 0 ----
    if (HA) {
        #pragma unroll
        for (int l = 0; l < 2; l++) {
            int p = tid + l * 256;               // 512 uint4 (128x32 half)
            int r = p >> 2, c8 = p & 3;
            int gr = row0 + r;
            uint4 v = make_uint4(0, 0, 0, 0);
            if (gr < M) v = *(const uint4*)&Ahg[(size_t)gr * K + c8 * 8];
            *(uint4*)&Ah[0][r][c8 * 8] = v;
        }
    } else {
        #pragma unroll
        for (int l = 0; l < 4; l++) {
            int p  = tid + l * 256;              // 1024 float4 (128x32 fp32)
            int r  = p >> 3, c4 = p & 7;
            int gr = row0 + r;
            float4 v = make_float4(0.f, 0.f, 0.f, 0.f);
            if (gr < M) v = *(const float4*)&Af[(size_t)gr * K + c4 * 4];
            *(uint2*)&Ah[0][r][c4 * 4] = pack4h(v);
        }
    }
    {
        int r = tid >> 3, c8 = tid & 7;          // 256 uint4 (32x64 half)
        uint4 v = *(const uint4*)&Bg[(size_t)r * N + col0 + c8 * 8];
        *(uint4*)&Bh[0][r][c8 * 8] = v;
    }
    __syncthreads();

    int buf = 0;
    for (int k0 = 0; k0 < K; k0 += TBK) {
        const int kn = k0 + TBK;
        const bool has_next = kn < K;

        // ---- prefetch next tile into registers ----
        uint4  pah[2];
        float4 paf[4];
        uint4  pbh;
        if (has_next) {
            if (HA) {
                #pragma unroll
                for (int l = 0; l < 2; l++) {
                    int p = tid + l * 256;
                    int r = p >> 2, c8 = p & 3;
                    int gr = row0 + r;
                    pah[l] = make_uint4(0, 0, 0, 0);
                    if (gr < M) pah[l] = *(const uint4*)&Ahg[(size_t)gr * K + kn + c8 * 8];
                }
            } else {
                #pragma unroll
                for (int l = 0; l < 4; l++) {
                    int p = tid + l * 256;
                    int r = p >> 3, c4 = p & 7;
                    int gr = row0 + r;
                    paf[l] = make_float4(0.f, 0.f, 0.f, 0.f);
                    if (gr < M) paf[l] = *(const float4*)&Af[(size_t)gr * K + kn + c4 * 4];
                }
            }
            {
                int r = tid >> 3, c8 = tid & 7;
                pbh = *(const uint4*)&Bg[(size_t)(kn + r) * N + col0 + c8 * 8];
            }
        }

        // ---- compute current buffer: 2 x k16 ----
        const uint32_t a_base = a_smem0 + buf * a_buf_sz;
        const uint32_t b_base = b_smem0 + buf * b_buf_sz;
        #pragma unroll
        for (int k16 = 0; k16 < 2; k16++) {
            const int kk = k16 * 16;
            uint32_t a[2][4];
            #pragma unroll
            for (int mi = 0; mi < 2; mi++) {
                uint32_t addr = a_base +
                    ((mbase + mi * 16 + lquad) * AROW + kk + lhalf) * 2;
                ldsm_x4(a[mi][0], a[mi][1], a[mi][2], a[mi][3], addr);
            }
            uint32_t b[4][2];
            #pragma unroll
            for (int pr = 0; pr < 2; pr++) {
                uint32_t addr = b_base +
                    ((kk + lquad) * BROW + nbase + pr * 16 + lhalf) * 2;
                ldsm_x4_t(b[pr * 2][0], b[pr * 2][1],
                          b[pr * 2 + 1][0], b[pr * 2 + 1][1], addr);
            }
            #pragma unroll
            for (int mi = 0; mi < 2; mi++)
                #pragma unroll
                for (int ni = 0; ni < 4; ni++)
                    mma_f16(acc[mi][ni], a[mi], b[ni]);
        }

        // ---- store next tile ----
        if (has_next) {
            int nb_ = buf ^ 1;
            if (HA) {
                #pragma unroll
                for (int l = 0; l < 2; l++) {
                    int p = tid + l * 256;
                    int r = p >> 2, c8 = p & 3;
                    *(uint4*)&Ah[nb_][r][c8 * 8] = pah[l];
                }
            } else {
                #pragma unroll
                for (int l = 0; l < 4; l++) {
                    int p = tid + l * 256;
                    int r = p >> 3, c4 = p & 7;
                    *(uint2*)&Ah[nb_][r][c4 * 4] = pack4h(paf[l]);
                }
            }
            {
                int r = tid >> 3, c8 = tid & 7;
                *(uint4*)&Bh[nb_][r][c8 * 8] = pbh;
            }
        }
        __syncthreads();
        buf ^= 1;
    }

    // ---- epilogue: fp16 C write ----
    #pragma unroll
    for (int mi = 0; mi < 2; mi++) {
        int r_lo = row0 + mbase + mi * 16 + g;
        int r_hi = r_lo + 8;
        #pragma unroll
        for (int ni = 0; ni < 4; ni++) {
            int c = col0 + nbase + ni * 8 + 2 * t;
            if (r_lo < M) {
                __half2 h = __floats2half2_rn(acc[mi][ni][0], acc[mi][ni][1]);
                *(__half2*)&C[(size_t)r_lo * N + c] = h;
            }
            if (r_hi < M) {
                __half2 h = __floats2half2_rn(acc[mi][ni][2], acc[mi][ni][3]);
                *(__half2*)&C[(size_t)r_hi * N + c] = h;
            }
        }
    }
}

// ---------------------------------------------------------------------------
// Fused aggregation: warp per node, atomic-free, fp16 gather, fp32 accumulate
// ---------------------------------------------------------------------------
__device__ __forceinline__ void acc8(float* f, uint4 u, float nm) {
    const __half2* h = (const __half2*)&u;
    #pragma unroll
    for (int j = 0; j < 4; j++) {
        float2 v = __half22float2(h[j]);
        f[j * 2]     += v.x * nm;
        f[j * 2 + 1] += v.y * nm;
    }
}

__global__ __launch_bounds__(256)
void node_agg_kernel(const float4* __restrict__ bias, int n, int do_relu) {
    int node = (blockIdx.x * blockDim.x + threadIdx.x) >> 5;
    if (node >= n) return;
    int lane = threadIdx.x & 31;

    const uint4* __restrict__ hh = (const uint4*)g_hh;
    const int beg = g_off[node];
    const int end = g_off[node + 1];
    const float dn = g_dinv[node];

    float f[8];
    #pragma unroll
    for (int j = 0; j < 8; j++) f[j] = 0.f;

    int e = beg;
    for (; e + 2 <= end; e += 2) {
        int s0 = g_csr[e];
        int s1 = g_csr[e + 1];
        float nm0 = dn * g_dinv[s0];
        float nm1 = dn * g_dinv[s1];
        uint4 u0 = hh[(size_t)s0 * DH8 + lane];
        uint4 u1 = hh[(size_t)s1 * DH8 + lane];
        acc8(f, u0, nm0);
        acc8(f, u1, nm1);
    }
    if (e < end) {
        int s = g_csr[e];
        float nm = dn * g_dinv[s];
        uint4 u = hh[(size_t)s * DH8 + lane];
        acc8(f, u, nm);
    }

    // self loop + bias
    {
        uint4 u = hh[(size_t)node * DH8 + lane];
        acc8(f, u, dn * dn);
        float4 b0 = bias[lane * 2];
        float4 b1 = bias[lane * 2 + 1];
        f[0] += b0.x; f[1] += b0.y; f[2] += b0.z; f[3] += b0.w;
        f[4] += b1.x; f[5] += b1.y; f[6] += b1.z; f[7] += b1.w;
    }

    if (do_relu) {
        #pragma unroll
        for (int j = 0; j < 8; j++) f[j] = fmaxf(f[j], 0.f);
    }

    uint4 o;
    __half2* oh = (__half2*)&o;
    #pragma unroll
    for (int j = 0; j < 4; j++)
        oh[j] = __floats2half2_rn(f[j * 2], f[j * 2 + 1]);
    ((uint4*)g_aggh)[(size_t)node * DH8 + lane] = o;
}

// ---------------------------------------------------------------------------
// Mean pool: 4 CTAs per graph, fp16 input, fp32 atomics
// ---------------------------------------------------------------------------
#define POOL_SPLIT 4

__global__ __launch_bounds__(128)
void pool_kernel() {
    int g = blockIdx.x >> 2;
    int p = blockIdx.x & 3;
    int c = threadIdx.x;
    int beg = g_gstart[g], end = g_gstart[g + 1];
    int len = end - beg;
    int chunk = (len + POOL_SPLIT - 1) / POOL_SPLIT;
    int lo = beg + p * chunk;
    int hi = min(lo + chunk, end);
    if (lo >= hi) return;
    const uint32_t* ah = (const uint32_t*)g_aggh;
    float ax = 0.f, ay = 0.f;
    for (int i = lo; i < hi; i++) {
        uint32_t u = ah[(size_t)i * 128 + c];
        float2 v = __half22float2(*(__half2*)&u);
        ax += v.x; ay += v.y;
    }
    atomicAdd(&g_pool[g * DHID + 2 * c],     ax);
    atomicAdd(&g_pool[g * DHID + 2 * c + 1], ay);
}

// ---------------------------------------------------------------------------
// Final linear (mean division folded in)
// ---------------------------------------------------------------------------
__global__ __launch_bounds__(256)
void final_kernel(const float* __restrict__ Wl, const float* __restrict__ bl,
                  float* __restrict__ out) {
    int d = blockIdx.x * blockDim.x + threadIdx.x;
    int g = blockIdx.y;
    const float* pg = g_pool + g * DHID;
    float acc = 0.f;
    #pragma unroll 8
    for (int c = 0; c < DHID; c++)
        acc += pg[c] * Wl[(size_t)c * DIN + d];
    float cnt = (float)(g_gstart[g + 1] - g_gstart[g]);
    out[(size_t)g * DIN + d] = acc / fmaxf(cnt, 1.f) + bl[d];
}

// ---------------------------------------------------------------------------
// Launch.  Layer-1 GEMM stays the 4th launch so ncu profiles it.
// ---------------------------------------------------------------------------
extern "C" void kernel_launch(void* const* d_in, const int* in_sizes, int n_in,
                              void* d_out, int out_size) {
    const float* x     = (const float*)d_in[0];
    const int*   ei    = (const int*)d_in[1];
    const int*   batch = (const int*)d_in[2];
    const float* W1 = (const float*)d_in[3];
    const float* b1 = (const float*)d_in[4];
    const float* W2 = (const float*)d_in[5];
    const float* b2 = (const float*)d_in[6];
    const float* W3 = (const float*)d_in[7];
    const float* b3 = (const float*)d_in[8];
    const float* Wl = (const float*)d_in[9];
    const float* bl = (const float*)d_in[10];
    float* out = (float*)d_out;

    const int n = in_sizes[0] / DIN;       // 50000
    const int E = in_sizes[1] / 2;         // 800000
    const int* src = ei;
    const int* dst = ei + E;

    dim3 gemm_grid(DHID / TBN, (n + TBM - 1) / TBM);     // (4, 391)
    const int agg_grid = (n * 32 + 255) / 256;
    const int nb = (n + 1023) / 1024;
    const int init_threads = DIN * DHID;

    __half *w1h, *w2h, *w3h, *aggh;
    cudaGetSymbolAddress((void**)&w1h,  g_w1h);
    cudaGetSymbolAddress((void**)&w2h,  g_w2h);
    cudaGetSymbolAddress((void**)&w3h,  g_w3h);
    cudaGetSymbolAddress((void**)&aggh, g_aggh);

    // launches 1-3
    init_kernel<<<(init_threads + 255) / 256, 256>>>(W1, W2, W3, n);
    histgmin_kernel<<<(E + 255) / 256, 256>>>(dst, batch, E, n);
    dinv_kernel<<<(n + 255) / 256, 256>>>(n);

    // launch 4: layer-1 GEMM (fp32 A path; profiled by ncu)
    gemm_tc_kernel<false><<<gemm_grid, 256>>>(x, (const __half*)nullptr, w1h,
                                              n, DIN, DHID);

    // CSR build
    scan1_kernel<<<nb, 1024>>>(n);
    scan2_kernel<<<1, 32>>>(nb, n);
    scan3_kernel<<<nb, 1024>>>(n);
    scatter_kernel<<<(E + 255) / 256, 256>>>(src, dst, E);
    gfix_kernel<<<1, 32>>>(n);

    // layer 1 aggregation
    node_agg_kernel<<<agg_grid, 256>>>((const float4*)b1, n, 1);

    // layer 2 (fp16 A path)
    gemm_tc_kernel<true><<<gemm_grid, 256>>>(nullptr, aggh, w2h, n, DHID, DHID);
    node_agg_kernel<<<agg_grid, 256>>>((const float4*)b2, n, 1);

    // layer 3 (no relu)
    gemm_tc_kernel<true><<<gemm_grid, 256>>>(nullptr, aggh, w3h, n, DHID, DHID);
    node_agg_kernel<<<agg_grid, 256>>>((const float4*)b3, n, 0);

    // mean pool + head
    pool_kernel<<<NGRAPHS * POOL_SPLIT, 128>>>();
    dim3 fgrid(DIN / 256, NGRAPHS);
    final_kernel<<<fgrid, 256>>>(Wl, bl, out);
}

// round 17
// speedup vs baseline: 1.0880x; 1.0880x over previous
#include <cuda_runtime.h>
#include <cuda_fp16.h>
#include <math.h>
#include <stdint.h>

// ---------------------------------------------------------------------------
// Problem constants
// ---------------------------------------------------------------------------
#define MAX_NODES 50000
#define MAX_EDGES 800000
#define DHID      256
#define DH8       32
#define NGRAPHS   64
#define DIN       768
#define MAXB      64

// ---------------------------------------------------------------------------
// Scratch (static device globals)
// ---------------------------------------------------------------------------
__device__ __align__(16) __half g_hh  [MAX_NODES * DHID];
__device__ __align__(16) __half g_aggh[MAX_NODES * DHID];
__device__ __align__(16) __half g_w1h [DIN * DHID];
__device__ __align__(16) __half g_w2h [DHID * DHID];
__device__ __align__(16) __half g_w3h [DHID * DHID];
__device__ float g_dinv[MAX_NODES];
__device__ int   g_edeg[MAX_NODES];
__device__ int   g_off [MAX_NODES + 1];
__device__ int   g_cur [MAX_NODES];
__device__ int   g_csr [MAX_EDGES];
__device__ float g_pool[NGRAPHS * DHID];
__device__ int   g_gstart[NGRAPHS + 1];
__device__ int   g_bsum[MAXB];
__device__ int   g_bofs[MAXB];

// ---------------------------------------------------------------------------
// cp.async helpers (16B, .cg = bypass L1)
// ---------------------------------------------------------------------------
__device__ __forceinline__ void cp_async16(uint32_t smem_dst, const void* gmem_src) {
    asm volatile("cp.async.cg.shared.global [%0], [%1], 16;"
                 :: "r"(smem_dst), "l"(gmem_src));
}
__device__ __forceinline__ void cp_async16_pred(uint32_t smem_dst, const void* gmem_src,
                                                bool pred) {
    int sz = pred ? 16 : 0;
    asm volatile("cp.async.cg.shared.global [%0], [%1], 16, %2;"
                 :: "r"(smem_dst), "l"(gmem_src), "r"(sz));
}
__device__ __forceinline__ void cp_async_commit() {
    asm volatile("cp.async.commit_group;");
}
__device__ __forceinline__ void cp_async_wait0() {
    asm volatile("cp.async.wait_group 0;");
}

// ---------------------------------------------------------------------------
// init: zero histogram/cursors/pool, init gstart, convert weights to fp16.
// ---------------------------------------------------------------------------
__global__ void init_kernel(const float* __restrict__ W1,
                            const float* __restrict__ W2,
                            const float* __restrict__ W3, int n) {
    int i = blockIdx.x * blockDim.x + threadIdx.x;
    if (i < n) { g_edeg[i] = 0; g_cur[i] = 0; }
    if (i <= NGRAPHS) g_gstart[i] = n;
    if (i < NGRAPHS * DHID) g_pool[i] = 0.f;
    if (i < DIN * DHID) g_w1h[i] = __float2half(W1[i]);
    if (i < DHID * DHID) {
        g_w2h[i] = __float2half(W2[i]);
        g_w3h[i] = __float2half(W3[i]);
    }
}

// hist + graph-start min, fused
__global__ void histgmin_kernel(const int* __restrict__ dst,
                                const int* __restrict__ batch, int E, int n) {
    int i = blockIdx.x * blockDim.x + threadIdx.x;
    if (i < E) atomicAdd(&g_edeg[dst[i]], 1);
    if (i < n) atomicMin(&g_gstart[batch[i]], i);
}

__global__ void dinv_kernel(int n) {
    int i = blockIdx.x * blockDim.x + threadIdx.x;
    if (i < n) g_dinv[i] = rsqrtf((float)(g_edeg[i] + 1));
}

__global__ __launch_bounds__(1024)
void scan1_kernel(int n) {
    __shared__ int ws[32];
    const int tid = threadIdx.x;
    const int b = blockIdx.x;
    const int i = b * 1024 + tid;
    int v = (i < n) ? g_edeg[i] : 0;
    int x = v;
    #pragma unroll
    for (int ofs = 1; ofs < 32; ofs <<= 1) {
        int y = __shfl_up_sync(0xFFFFFFFFu, x, ofs);
        if ((tid & 31) >= ofs) x += y;
    }
    if ((tid & 31) == 31) ws[tid >> 5] = x;
    __syncthreads();
    if (tid < 32) {
        int w = ws[tid];
        #pragma unroll
        for (int ofs = 1; ofs < 32; ofs <<= 1) {
            int y = __shfl_up_sync(0xFFFFFFFFu, w, ofs);
            if (tid >= ofs) w += y;
        }
        ws[tid] = w;
    }
    __syncthreads();
    int incl = x + ((tid >= 32) ? ws[(tid >> 5) - 1] : 0);
    if (i < n) g_off[i] = incl - v;
    if (tid == 1023) g_bsum[b] = incl;
}

__global__ void scan2_kernel(int nb, int n) {
    if (threadIdx.x == 0) {
        int run = 0;
        for (int b = 0; b < nb; b++) { g_bofs[b] = run; run += g_bsum[b]; }
        g_off[n] = run;
    }
}

__global__ __launch_bounds__(1024)
void scan3_kernel(int n) {
    int i = blockIdx.x * blockDim.x + threadIdx.x;
    if (i < n) g_off[i] += g_bofs[i >> 10];
}

__global__ void scatter_kernel(const int* __restrict__ src,
                               const int* __restrict__ dst, int E) {
    int i = blockIdx.x * blockDim.x + threadIdx.x;
    if (i < E) {
        int d = dst[i];
        int pos = g_off[d] + atomicAdd(&g_cur[d], 1);
        g_csr[pos] = src[i];
    }
}

__global__ void gfix_kernel(int n) {
    if (threadIdx.x == 0 && blockIdx.x == 0) {
        g_gstart[NGRAPHS] = n;
        for (int g = NGRAPHS - 1; g >= 0; g--)
            if (g_gstart[g] > g_gstart[g + 1]) g_gstart[g] = g_gstart[g + 1];
    }
}

// ---------------------------------------------------------------------------
// fp16 tensor-core GEMM (fp32 accumulate): g_hh = A @ B, C stored fp16.
// CTA tile 128x128x64 (TBK doubled: half the syncs, 2x latency window).
// 8 warps, warp tile 32x64 via m16n8k16 + ldmatrix (R13 shape).
// HA=true : A fp16 via cp.async; HA=false: A fp32 LDG, two-wave in-tile
// software pipeline (LDG w1 -> compute k0,k1 -> STS w1 + LDG w2 ->
// compute k2,k3 -> STS w2).  B always cp.async fp16.
// ---------------------------------------------------------------------------
#define TBM 128
#define TBN 128
#define TBK 64
#define AROW (TBK + 8)        // 72 half = 144 B (16B mult; 36w%32=4r distinct)
#define BROW (TBN + 8)        // 136 half = 272 B (68w%32=4r distinct)
#define A_TILE (TBM * AROW * 2)   // 18432 B
#define B_TILE (TBK * BROW * 2)   // 17408 B
#define SMEM_DYN (2 * (A_TILE + B_TILE))   // 71680 B

__device__ __forceinline__ void ldsm_x4(uint32_t& r0, uint32_t& r1,
                                        uint32_t& r2, uint32_t& r3, uint32_t addr) {
    asm volatile("ldmatrix.sync.aligned.m8n8.x4.shared.b16 {%0,%1,%2,%3}, [%4];"
                 : "=r"(r0), "=r"(r1), "=r"(r2), "=r"(r3) : "r"(addr));
}

__device__ __forceinline__ void ldsm_x4_t(uint32_t& r0, uint32_t& r1,
                                          uint32_t& r2, uint32_t& r3, uint32_t addr) {
    asm volatile("ldmatrix.sync.aligned.m8n8.x4.trans.shared.b16 {%0,%1,%2,%3}, [%4];"
                 : "=r"(r0), "=r"(r1), "=r"(r2), "=r"(r3) : "r"(addr));
}

__device__ __forceinline__ void mma_f16(float* c, const uint32_t* a, const uint32_t* b) {
    asm volatile(
        "mma.sync.aligned.m16n8k16.row.col.f32.f16.f16.f32 "
        "{%0,%1,%2,%3}, {%4,%5,%6,%7}, {%8,%9}, {%0,%1,%2,%3};"
        : "+f"(c[0]), "+f"(c[1]), "+f"(c[2]), "+f"(c[3])
        : "r"(a[0]), "r"(a[1]), "r"(a[2]), "r"(a[3]), "r"(b[0]), "r"(b[1]));
}

__device__ __forceinline__ uint2 pack4h(float4 v) {
    __half2 h0 = __floats2half2_rn(v.x, v.y);
    __half2 h1 = __floats2half2_rn(v.z, v.w);
    uint2 u;
    u.x = *(uint32_t*)&h0;
    u.y = *(uint32_t*)&h1;
    return u;
}

template <bool HA>
__global__ __launch_bounds__(256, 2)
void gemm_tc_kernel(const float* __restrict__ Af, const __half* __restrict__ Ahg,
                    const __half* __restrict__ Bg, int M, int K, int N) {
    extern __shared__ __align__(16) char dsm[];
    __half* const smh = (__half*)dsm;
    __half* __restrict__ C = g_hh;

    const int tid  = threadIdx.x;
    const int warp = tid >> 5;
    const int lane = tid & 31;
    const int g    = lane >> 2;
    const int t    = lane & 3;
    const int wm   = warp >> 1;
    const int wn   = warp & 1;
    const int row0 = blockIdx.y * TBM;
    const int col0 = blockIdx.x * TBN;
    const int mbase = wm * 32;
    const int nbase = wn * 64;

    const int lquad = lane & 15;
    const int lhalf = (lane >> 4) << 3;

    const uint32_t smem0 = (uint32_t)__cvta_generic_to_shared(dsm);
    const uint32_t abuf[2] = {0u, (uint32_t)A_TILE};
    const uint32_t bbuf[2] = {2u * A_TILE, 2u * A_TILE + B_TILE};

    float acc[2][8][4];
    #pragma unroll
    for (int mi = 0; mi < 2; mi++)
        #pragma unroll
        for (int ni = 0; ni < 8; ni++)
            #pragma unroll
            for (int r = 0; r < 4; r++) acc[mi][ni][r] = 0.f;

    // ---- loaders ----
    // A fp16 (HA): 128x64 half = 1024 uint4, 4/thread, cp.async
    auto loadA_h = [&](int kk, int bi) {
        #pragma unroll
        for (int l = 0; l < 4; l++) {
            int p = tid + l * 256;
            int r = p >> 3, c8 = p & 7;
            int gr = row0 + r;
            uint32_t d = smem0 + abuf[bi] + (r * AROW + c8 * 8) * 2;
            const __half* s = &Ahg[(size_t)(gr < M ? gr : 0) * K + kk + c8 * 8];
            cp_async16_pred(d, s, gr < M);
        }
    };
    // A fp32 wave (half=0 -> cols 0..31, half=1 -> cols 32..63): LDG into regs
    auto ldgA_f = [&](int kk, int half, float4* pf) {
        #pragma unroll
        for (int l = 0; l < 4; l++) {
            int p = tid + l * 256;
            int r = p >> 3, c4 = p & 7;
            int gr = row0 + r;
            pf[l] = make_float4(0.f, 0.f, 0.f, 0.f);
            if (gr < M)
                pf[l] = *(const float4*)&Af[(size_t)gr * K + kk + half * 32 + c4 * 4];
        }
    };
    auto stsA_f = [&](int bi, int half, const float4* pf) {
        #pragma unroll
        for (int l = 0; l < 4; l++) {
            int p = tid + l * 256;
            int r = p >> 3, c4 = p & 7;
            *(uint2*)&smh[(abuf[bi] >> 1) + r * AROW + half * 32 + c4 * 4] =
                pack4h(pf[l]);
        }
    };
    // B: 64x128 half = 1024 uint4, 4/thread, cp.async
    auto loadB = [&](int kk, int bi) {
        #pragma unroll
        for (int l = 0; l < 4; l++) {
            int p = tid + l * 256;
            int r = p >> 4, c8 = p & 15;
            uint32_t d = smem0 + bbuf[bi] + (r * BROW + c8 * 8) * 2;
            cp_async16(d, &Bg[(size_t)(kk + r) * N + col0 + c8 * 8]);
        }
    };
    // compute two k16 steps (k16i, k16i+1) from buffer bi
    auto compute2 = [&](int bi, int k16i) {
        #pragma unroll
        for (int k16 = k16i; k16 < k16i + 2; k16++) {
            const int kk = k16 * 16;
            uint32_t a[2][4];
            #pragma unroll
            for (int mi = 0; mi < 2; mi++) {
                uint32_t addr = smem0 + abuf[bi] +
                    ((mbase + mi * 16 + lquad) * AROW + kk + lhalf) * 2;
                ldsm_x4(a[mi][0], a[mi][1], a[mi][2], a[mi][3], addr);
            }
            uint32_t b[8][2];
            #pragma unroll
            for (int pr = 0; pr < 4; pr++) {
                uint32_t addr = smem0 + bbuf[bi] +
                    ((kk + lquad) * BROW + nbase + pr * 16 + lhalf) * 2;
                ldsm_x4_t(b[pr * 2][0], b[pr * 2][1],
                          b[pr * 2 + 1][0], b[pr * 2 + 1][1], addr);
            }
            #pragma unroll
            for (int mi = 0; mi < 2; mi++)
                #pragma unroll
                for (int ni = 0; ni < 8; ni++)
                    mma_f16(acc[mi][ni], a[mi], b[ni]);
        }
    };

    // ---- prologue: tile 0 -> buf 0 ----
    if (HA) {
        loadA_h(0, 0);
    } else {
        float4 pf[4];
        ldgA_f(0, 0, pf); stsA_f(0, 0, pf);
        ldgA_f(0, 1, pf); stsA_f(0, 1, pf);
    }
    loadB(0, 0);
    cp_async_commit();
    cp_async_wait0();
    __syncthreads();

    const int nch = K / TBK;
    int buf = 0;
    for (int i = 0; i < nch; i++) {
        const int kn = (i + 1) * TBK;
        const bool has_next = i + 1 < nch;
        const int nb_ = buf ^ 1;

        float4 pf[4];
        if (has_next) {
            if (HA) loadA_h(kn, nb_);
            else    ldgA_f(kn, 0, pf);          // wave 1 LDG
            loadB(kn, nb_);
            cp_async_commit();
        }

        compute2(buf, 0);                        // k16 0,1

        if (!HA && has_next) {
            stsA_f(nb_, 0, pf);                  // wave 1 STS
            ldgA_f(kn, 1, pf);                   // wave 2 LDG
        }

        compute2(buf, 2);                        // k16 2,3

        if (!HA && has_next) stsA_f(nb_, 1, pf); // wave 2 STS
        if (has_next) cp_async_wait0();
        __syncthreads();
        buf = nb_;
    }

    // ---- epilogue: fp16 C write ----
    #pragma unroll
    for (int mi = 0; mi < 2; mi++) {
        int r_lo = row0 + mbase + mi * 16 + g;
        int r_hi = r_lo + 8;
        #pragma unroll
        for (int ni = 0; ni < 8; ni++) {
            int c = col0 + nbase + ni * 8 + 2 * t;
            if (r_lo < M) {
                __half2 h = __floats2half2_rn(acc[mi][ni][0], acc[mi][ni][1]);
                *(__half2*)&C[(size_t)r_lo * N + c] = h;
            }
            if (r_hi < M) {
                __half2 h = __floats2half2_rn(acc[mi][ni][2], acc[mi][ni][3]);
                *(__half2*)&C[(size_t)r_hi * N + c] = h;
            }
        }
    }
}

// ---------------------------------------------------------------------------
// Fused aggregation: warp per node, atomic-free, fp16 gather
// ---------------------------------------------------------------------------
__device__ __forceinline__ void acc8(float* f, uint4 u, float nm) {
    const __half2* h = (const __half2*)&u;
    #pragma unroll
    for (int j = 0; j < 4; j++) {
        float2 v = __half22float2(h[j]);
        f[j * 2]     += v.x * nm;
        f[j * 2 + 1] += v.y * nm;
    }
}

__global__ __launch_bounds__(256)
void node_agg_kernel(const float4* __restrict__ bias, int n, int do_relu) {
    int node = (blockIdx.x * blockDim.x + threadIdx.x) >> 5;
    if (node >= n) return;
    int lane = threadIdx.x & 31;

    const uint4* __restrict__ hh = (const uint4*)g_hh;
    const int beg = g_off[node];
    const int end = g_off[node + 1];
    const float dn = g_dinv[node];

    float f[8];
    #pragma unroll
    for (int j = 0; j < 8; j++) f[j] = 0.f;

    int e = beg;
    for (; e + 2 <= end; e += 2) {
        int s0 = g_csr[e];
        int s1 = g_csr[e + 1];
        float nm0 = dn * g_dinv[s0];
        float nm1 = dn * g_dinv[s1];
        uint4 u0 = hh[(size_t)s0 * DH8 + lane];
        uint4 u1 = hh[(size_t)s1 * DH8 + lane];
        acc8(f, u0, nm0);
        acc8(f, u1, nm1);
    }
    if (e < end) {
        int s = g_csr[e];
        float nm = dn * g_dinv[s];
        uint4 u = hh[(size_t)s * DH8 + lane];
        acc8(f, u, nm);
    }

    {
        uint4 u = hh[(size_t)node * DH8 + lane];
        acc8(f, u, dn * dn);
        float4 b0 = bias[lane * 2];
        float4 b1 = bias[lane * 2 + 1];
        f[0] += b0.x; f[1] += b0.y; f[2] += b0.z; f[3] += b0.w;
        f[4] += b1.x; f[5] += b1.y; f[6] += b1.z; f[7] += b1.w;
    }

    if (do_relu) {
        #pragma unroll
        for (int j = 0; j < 8; j++) f[j] = fmaxf(f[j], 0.f);
    }

    uint4 o;
    __half2* oh = (__half2*)&o;
    #pragma unroll
    for (int j = 0; j < 4; j++)
        oh[j] = __floats2half2_rn(f[j * 2], f[j * 2 + 1]);
    ((uint4*)g_aggh)[(size_t)node * DH8 + lane] = o;
}

// ---------------------------------------------------------------------------
// Mean pool: 4 CTAs per graph, fp16 input, fp32 atomics
// ---------------------------------------------------------------------------
#define POOL_SPLIT 4

__global__ __launch_bounds__(128)
void pool_kernel() {
    int g = blockIdx.x >> 2;
    int p = blockIdx.x & 3;
    int c = threadIdx.x;
    int beg = g_gstart[g], end = g_gstart[g + 1];
    int len = end - beg;
    int chunk = (len + POOL_SPLIT - 1) / POOL_SPLIT;
    int lo = beg + p * chunk;
    int hi = min(lo + chunk, end);
    if (lo >= hi) return;
    const uint32_t* ah = (const uint32_t*)g_aggh;
    float ax = 0.f, ay = 0.f;
    for (int i = lo; i < hi; i++) {
        uint32_t u = ah[(size_t)i * 128 + c];
        float2 v = __half22float2(*(__half2*)&u);
        ax += v.x; ay += v.y;
    }
    atomicAdd(&g_pool[g * DHID + 2 * c],     ax);
    atomicAdd(&g_pool[g * DHID + 2 * c + 1], ay);
}

// ---------------------------------------------------------------------------
// Final linear (mean division folded in)
// ---------------------------------------------------------------------------
__global__ __launch_bounds__(256)
void final_kernel(const float* __restrict__ Wl, const float* __restrict__ bl,
                  float* __restrict__ out) {
    int d = blockIdx.x * blockDim.x + threadIdx.x;
    int g = blockIdx.y;
    const float* pg = g_pool + g * DHID;
    float acc = 0.f;
    #pragma unroll 8
    for (int c = 0; c < DHID; c++)
        acc += pg[c] * Wl[(size_t)c * DIN + d];
    float cnt = (float)(g_gstart[g + 1] - g_gstart[g]);
    out[(size_t)g * DIN + d] = acc / fmaxf(cnt, 1.f) + bl[d];
}

// ---------------------------------------------------------------------------
// Launch.  Layer-1 GEMM stays the 4th launch so ncu profiles it.
// ---------------------------------------------------------------------------
extern "C" void kernel_launch(void* const* d_in, const int* in_sizes, int n_in,
                              void* d_out, int out_size) {
    const float* x     = (const float*)d_in[0];
    const int*   ei    = (const int*)d_in[1];
    const int*   batch = (const int*)d_in[2];
    const float* W1 = (const float*)d_in[3];
    const float* b1 = (const float*)d_in[4];
    const float* W2 = (const float*)d_in[5];
    const float* b2 = (const float*)d_in[6];
    const float* W3 = (const float*)d_in[7];
    const float* b3 = (const float*)d_in[8];
    const float* Wl = (const float*)d_in[9];
    const float* bl = (const float*)d_in[10];
    float* out = (float*)d_out;

    const int n = in_sizes[0] / DIN;       // 50000
    const int E = in_sizes[1] / 2;         // 800000
    const int* src = ei;
    const int* dst = ei + E;

    dim3 gemm_grid(DHID / TBN, (n + TBM - 1) / TBM);   // (2, 391)
    const int agg_grid = (n * 32 + 255) / 256;
    const int nb = (n + 1023) / 1024;
    const int init_threads = DIN * DHID;

    __half *w1h, *w2h, *w3h, *aggh;
    cudaGetSymbolAddress((void**)&w1h,  g_w1h);
    cudaGetSymbolAddress((void**)&w2h,  g_w2h);
    cudaGetSymbolAddress((void**)&w3h,  g_w3h);
    cudaGetSymbolAddress((void**)&aggh, g_aggh);

    cudaFuncSetAttribute(gemm_tc_kernel<false>,
                         cudaFuncAttributeMaxDynamicSharedMemorySize, SMEM_DYN);
    cudaFuncSetAttribute(gemm_tc_kernel<true>,
                         cudaFuncAttributeMaxDynamicSharedMemorySize, SMEM_DYN);

    // launches 1-3
    init_kernel<<<(init_threads + 255) / 256, 256>>>(W1, W2, W3, n);
    histgmin_kernel<<<(E + 255) / 256, 256>>>(dst, batch, E, n);
    dinv_kernel<<<(n + 255) / 256, 256>>>(n);

    // launch 4: layer-1 GEMM (fp32 A path; profiled by ncu)
    gemm_tc_kernel<false><<<gemm_grid, 256, SMEM_DYN>>>(x, (const __half*)nullptr,
                                                        w1h, n, DIN, DHID);

    // CSR build
    scan1_kernel<<<nb, 1024>>>(n);
    scan2_kernel<<<1, 32>>>(nb, n);
    scan3_kernel<<<nb, 1024>>>(n);
    scatter_kernel<<<(E + 255) / 256, 256>>>(src, dst, E);
    gfix_kernel<<<1, 32>>>(n);

    // layer 1 aggregation
    node_agg_kernel<<<agg_grid, 256>>>((const float4*)b1, n, 1);

    // layer 2 (fp16 A path)
    gemm_tc_kernel<true><<<gemm_grid, 256, SMEM_DYN>>>(nullptr, aggh, w2h,
                                                       n, DHID, DHID);
    node_agg_kernel<<<agg_grid, 256>>>((const float4*)b2, n, 1);

    // layer 3 (no relu)
    gemm_tc_kernel<true><<<gemm_grid, 256, SMEM_DYN>>>(nullptr, aggh, w3h,
                                                       n, DHID, DHID);
    node_agg_kernel<<<agg_grid, 256>>>((const float4*)b3, n, 0);

    // mean pool + head
    pool_kernel<<<NGRAPHS * POOL_SPLIT, 128>>>();
    dim3 fgrid(DIN / 256, NGRAPHS);
    final_kernel<<<fgrid, 256>>>(Wl, bl, out);
}